// round 16
// baseline (speedup 1.0000x reference)
#include <cuda_runtime.h>
#include <cuda_fp16.h>
#include <cstdint>

// Problem shape (fixed by the dataset)
constexpr int B = 8, C = 16, H = 512, W = 512;
constexpr int HW = H * W;            // 262144 = 2^18
constexpr int CHW = C * HW;
constexpr int NPIX = B * HW;         // 2,097,152
constexpr int NOUT = B * CHW;        // 33,554,432

// Asymmetric pipeline split: group A = batches 0-5, group B = batches 6-7.
constexpr int BA = 6;                          // batches in group A
constexpr int A_PIX = BA * HW;                 // 1,572,864
constexpr int A_SPLAT_BLKS = A_PIX / 256;      // 6144
constexpr int B_SPLAT_BLKS = (B - BA) * HW / 256;   // 2048
constexpr int A_TPOSE_BLKS = BA * 512;         // 3072 (512-pixel tiles)
constexpr int B_TPOSE_BLKS = (B - BA) * 512;   // 1024
constexpr int A_ZERO_BLKS  = A_PIX / 1024;     // 1536 (1024 pixels/block)
constexpr int B_ZERO_BLKS  = (B - BA) * HW / 1024;  // 512

// Split-plane fp16 scratch, 64 MiB (R10 layout):
//   LO plane (ch 0..7):  uint4[p]          for global pixel p
//   HI plane (ch 8..15): uint4[NPIX + p]
// Zero at module load. K3 re-zeroes group A, K1 re-zeroes group B (before
// K2 splats into it) -> "scratch==0 on entry" holds for every replay.
__device__ __half g_scratch[NOUT];
constexpr size_t HI_OFF_H2 = (size_t)NPIX * 4;   // half2 offset of HI plane

// ---------------------------------------------------------------------------
// 16-byte fp16 vector reduction (hard max RED width): 8 halves per request.
// ---------------------------------------------------------------------------
__device__ __forceinline__ void red_v4h2(__half2* p, __half2 a, __half2 b,
                                         __half2 c, __half2 d) {
    unsigned ra = *(unsigned*)&a, rb = *(unsigned*)&b;
    unsigned rc = *(unsigned*)&c, rd = *(unsigned*)&d;
    asm volatile("red.global.add.noftz.v4.f16x2 [%0], {%1, %2, %3, %4};"
                 :: "l"(p), "r"(ra), "r"(rb), "r"(rc), "r"(rd) : "memory");
}

// ---------------------------------------------------------------------------
// Role: splat one pixel (R13 body). idx = global pixel index (b*HW + hw).
// ---------------------------------------------------------------------------
__device__ __forceinline__ void splat_pixel(const float* __restrict__ x,
                                            const float2* __restrict__ grid,
                                            int idx) {
    int b  = idx >> 18;        // / HW
    int hw = idx & (HW - 1);   // % HW

    float2 g = __ldcs(grid + idx);   // single-use: evict-first

    float gi = fminf(fmaxf((g.x + 1.0f) * 0.5f * (float)H + 1.0f, 0.0f), (float)(H + 1));
    float gj = fminf(fmaxf((g.y + 1.0f) * 0.5f * (float)W + 1.0f, 0.0f), (float)(W + 1));

    int   fi  = (int)gi;            // gi >= 0 so trunc == floor
    int   fj  = (int)gj;
    float fri = gi - (float)fi;
    float frj = gj - (float)fj;

    float w00 = (1.0f - fri) * (1.0f - frj);
    float w01 = (1.0f - fri) * frj;
    float w10 = fri * (1.0f - frj);
    float w11 = fri * frj;

    int oi0 = fi - 1;
    int oj0 = fj - 1;
    bool i0 = (unsigned)oi0       < (unsigned)H;
    bool i1 = (unsigned)(oi0 + 1) < (unsigned)H;
    bool j0 = (unsigned)oj0       < (unsigned)W;
    bool j1 = (unsigned)(oj0 + 1) < (unsigned)W;

    const float* xp = x + (size_t)b * CHW + hw;
    float v[C];
#pragma unroll
    for (int c = 0; c < C; c++) v[c] = __ldcs(xp + c * HW);

    size_t p00 = (size_t)b * HW + (size_t)oi0 * W + oj0;
    __half2* l00 = (__half2*)g_scratch + p00 * 4;              // LO, (i0,j0)
    __half2* l10 = l00 + (size_t)W * 4;                        // LO, (i1,j0)
    __half2* h00 = (__half2*)g_scratch + HI_OFF_H2 + p00 * 4;  // HI: +32MB
    __half2* h10 = h00 + (size_t)W * 4;

#define PACK4(dst, wgt, half)                                                   \
    {                                                                           \
        _Pragma("unroll")                                                       \
        for (int j = 0; j < 4; j++)                                             \
            dst[j] = __floats2half2_rn(v[8*(half) + 2*j]     * (wgt),           \
                                       v[8*(half) + 2*j + 1] * (wgt));          \
    }

    if (j0) {
        __half2 a[4], c[4];
        if (i0) { PACK4(a, w00, 0); red_v4h2(l00, a[0], a[1], a[2], a[3]); }
        if (i1) { PACK4(c, w10, 0); red_v4h2(l10, c[0], c[1], c[2], c[3]); }
        if (i0) { PACK4(a, w00, 1); red_v4h2(h00, a[0], a[1], a[2], a[3]); }
        if (i1) { PACK4(c, w10, 1); red_v4h2(h10, c[0], c[1], c[2], c[3]); }
    }
    if (j1) {
        __half2 a[4], c[4];
        if (i0) { PACK4(a, w01, 0); red_v4h2(l00 + 4, a[0], a[1], a[2], a[3]); }
        if (i1) { PACK4(c, w11, 0); red_v4h2(l10 + 4, c[0], c[1], c[2], c[3]); }
        if (i0) { PACK4(a, w01, 1); red_v4h2(h00 + 4, a[0], a[1], a[2], a[3]); }
        if (i1) { PACK4(c, w11, 1); red_v4h2(h10 + 4, c[0], c[1], c[2], c[3]); }
    }
#undef PACK4
}

// ---------------------------------------------------------------------------
// Role: zero 1024 pixels of scratch per block (both planes, 32 KiB/block).
// Region starts at pixel pix_base; rb = role-local block id.
// ---------------------------------------------------------------------------
__device__ __forceinline__ void zero_role(int rb, int rt, int pix_base) {
    uint4* u = (uint4*)g_scratch;
    const uint4 z = make_uint4(0u, 0u, 0u, 0u);
#pragma unroll
    for (int k = 0; k < 4; k++) {
        int idx = pix_base + rb * 1024 + k * 256 + rt;   // coalesced
        u[idx]        = z;          // LO plane
        u[NPIX + idx] = z;          // HI plane
    }
}

// ---------------------------------------------------------------------------
// Role: transpose one 512-pixel tile (256 threads; R13 config).
// tb = role-local tile id; b_base = first batch of the group.
// ---------------------------------------------------------------------------
__device__ __forceinline__ void transpose_role(int tb, int t, int b_base,
                                               float* __restrict__ out) {
    __shared__ __half2 sm[8][512];   // 16 KiB

    const __half2* s = (const __half2*)g_scratch;
    int b    = b_base + (tb >> 9);   // 512 tiles per batch
    int base = (tb & 511) * 512;     // pixel base within batch

#pragma unroll
    for (int q = 0; q < 2; q++) {
        int p = t + 256 * q;
        size_t gp = (size_t)b * HW + base + p;
        uint4 a  = __ldcs((const uint4*)(s + gp * 4));               // ch 0..7
        uint4 bq = __ldcs((const uint4*)(s + HI_OFF_H2 + gp * 4));   // ch 8..15
        sm[0][p] = *(__half2*)&a.x;  sm[1][p] = *(__half2*)&a.y;
        sm[2][p] = *(__half2*)&a.z;  sm[3][p] = *(__half2*)&a.w;
        sm[4][p] = *(__half2*)&bq.x; sm[5][p] = *(__half2*)&bq.y;
        sm[6][p] = *(__half2*)&bq.z; sm[7][p] = *(__half2*)&bq.w;
    }
    __syncthreads();

    float* ob = out + (size_t)b * CHW + base;
    int sub = t >> 7;                // 0: channel pairs 0..3, 1: pairs 4..7
    int tt  = t & 127;

#pragma unroll
    for (int r2 = 0; r2 < 4; r2++) {
        int r = sub * 4 + r2;
        uint4 raw = *(const uint4*)&sm[r][4 * tt];
        float2 f0 = __half22float2(*(__half2*)&raw.x);
        float2 f1 = __half22float2(*(__half2*)&raw.y);
        float2 f2 = __half22float2(*(__half2*)&raw.z);
        float2 f3 = __half22float2(*(__half2*)&raw.w);
        float4 ve = make_float4(f0.x, f1.x, f2.x, f3.x);  // channel 2r
        float4 vo = make_float4(f0.y, f1.y, f2.y, f3.y);  // channel 2r+1
        __stcs((float4*)(ob + (size_t)(2*r)     * HW) + tt, ve);
        __stcs((float4*)(ob + (size_t)(2*r + 1) * HW) + tt, vo);
    }
}

// ---------------------------------------------------------------------------
// K1: splat(batches 0-5)    || zero(scratch 6-7).           Disjoint data.
// K2: splat(batches 6-7)    || transpose(batches 0-5).      Disjoint data.
// K3: transpose(batches 6-7)|| zero(scratch 0-5, for next launch/replay).
// No cross-block waiting; kernel boundaries provide all ordering.
// ---------------------------------------------------------------------------
__global__ __launch_bounds__(256, 8)
void k1(const float* __restrict__ x, const float2* __restrict__ grid) {
    int bid = blockIdx.x;
    if (bid < A_SPLAT_BLKS) splat_pixel(x, grid, bid * 256 + threadIdx.x);
    else                    zero_role(bid - A_SPLAT_BLKS, threadIdx.x, A_PIX);
}

__global__ __launch_bounds__(256, 8)
void k2(const float* __restrict__ x, const float2* __restrict__ grid,
        float* __restrict__ out) {
    int bid = blockIdx.x;
    if (bid < B_SPLAT_BLKS) splat_pixel(x, grid, A_PIX + bid * 256 + threadIdx.x);
    else                    transpose_role(bid - B_SPLAT_BLKS, threadIdx.x, 0, out);
}

__global__ __launch_bounds__(256, 8)
void k3(float* __restrict__ out) {
    int bid = blockIdx.x;
    if (bid < B_TPOSE_BLKS) transpose_role(bid, threadIdx.x, BA, out);
    else                    zero_role(bid - B_TPOSE_BLKS, threadIdx.x, 0);
}

extern "C" void kernel_launch(void* const* d_in, const int* in_sizes, int n_in,
                              void* d_out, int out_size) {
    const float*  x    = (const float*)d_in[0];
    const float2* grid = (const float2*)d_in[1];
    float*        out  = (float*)d_out;

    k1<<<A_SPLAT_BLKS + B_ZERO_BLKS, 256>>>(x, grid);        // 6656 blocks
    k2<<<B_SPLAT_BLKS + A_TPOSE_BLKS, 256>>>(x, grid, out);  // 5120 blocks
    k3<<<B_TPOSE_BLKS + A_ZERO_BLKS, 256>>>(out);            // 2560 blocks
}

// round 17
// speedup vs baseline: 1.0163x; 1.0163x over previous
#include <cuda_runtime.h>
#include <cuda_fp16.h>
#include <cstdint>

// Problem shape (fixed by the dataset)
constexpr int B = 8, C = 16, H = 512, W = 512;
constexpr int HW = H * W;            // 262144 = 2^18
constexpr int CHW = C * HW;
constexpr int NPIX = B * HW;         // 2,097,152
constexpr int NOUT = B * CHW;        // 33,554,432

// Asymmetric pipeline split 5/3: group A = batches 0-4, group B = batches 5-7.
// (4/4 measured 131.9us, 6/2 measured 135.3us; the pipeline model
//  T = splat(A) + max(splat(B), transpose(A)) + transpose(B) is minimized
//  between them at 5/3.)
constexpr int BA = 5;                          // batches in group A
constexpr int A_PIX = BA * HW;                 // 1,310,720
constexpr int A_SPLAT_BLKS = A_PIX / 256;      // 5120
constexpr int B_SPLAT_BLKS = (B - BA) * HW / 256;   // 3072
constexpr int A_TPOSE_BLKS = BA * 512;         // 2560 (512-pixel tiles)
constexpr int B_TPOSE_BLKS = (B - BA) * 512;   // 1536
constexpr int A_ZERO_BLKS  = A_PIX / 1024;     // 1280 (1024 pixels/block)
constexpr int B_ZERO_BLKS  = (B - BA) * HW / 1024;  // 768

// Split-plane fp16 scratch, 64 MiB (R10 layout):
//   LO plane (ch 0..7):  uint4[p]          for global pixel p
//   HI plane (ch 8..15): uint4[NPIX + p]
// Zero at module load. K3 re-zeroes group A, K1 re-zeroes group B (before
// K2 splats into it) -> "scratch==0 on entry" holds for every replay.
__device__ __half g_scratch[NOUT];
constexpr size_t HI_OFF_H2 = (size_t)NPIX * 4;   // half2 offset of HI plane

// ---------------------------------------------------------------------------
// 16-byte fp16 vector reduction (hard max RED width): 8 halves per request.
// ---------------------------------------------------------------------------
__device__ __forceinline__ void red_v4h2(__half2* p, __half2 a, __half2 b,
                                         __half2 c, __half2 d) {
    unsigned ra = *(unsigned*)&a, rb = *(unsigned*)&b;
    unsigned rc = *(unsigned*)&c, rd = *(unsigned*)&d;
    asm volatile("red.global.add.noftz.v4.f16x2 [%0], {%1, %2, %3, %4};"
                 :: "l"(p), "r"(ra), "r"(rb), "r"(rc), "r"(rd) : "memory");
}

// ---------------------------------------------------------------------------
// Role: splat one pixel (R13 body). idx = global pixel index (b*HW + hw).
// ---------------------------------------------------------------------------
__device__ __forceinline__ void splat_pixel(const float* __restrict__ x,
                                            const float2* __restrict__ grid,
                                            int idx) {
    int b  = idx >> 18;        // / HW
    int hw = idx & (HW - 1);   // % HW

    float2 g = __ldcs(grid + idx);   // single-use: evict-first

    float gi = fminf(fmaxf((g.x + 1.0f) * 0.5f * (float)H + 1.0f, 0.0f), (float)(H + 1));
    float gj = fminf(fmaxf((g.y + 1.0f) * 0.5f * (float)W + 1.0f, 0.0f), (float)(W + 1));

    int   fi  = (int)gi;            // gi >= 0 so trunc == floor
    int   fj  = (int)gj;
    float fri = gi - (float)fi;
    float frj = gj - (float)fj;

    float w00 = (1.0f - fri) * (1.0f - frj);
    float w01 = (1.0f - fri) * frj;
    float w10 = fri * (1.0f - frj);
    float w11 = fri * frj;

    int oi0 = fi - 1;
    int oj0 = fj - 1;
    bool i0 = (unsigned)oi0       < (unsigned)H;
    bool i1 = (unsigned)(oi0 + 1) < (unsigned)H;
    bool j0 = (unsigned)oj0       < (unsigned)W;
    bool j1 = (unsigned)(oj0 + 1) < (unsigned)W;

    const float* xp = x + (size_t)b * CHW + hw;
    float v[C];
#pragma unroll
    for (int c = 0; c < C; c++) v[c] = __ldcs(xp + c * HW);

    size_t p00 = (size_t)b * HW + (size_t)oi0 * W + oj0;
    __half2* l00 = (__half2*)g_scratch + p00 * 4;              // LO, (i0,j0)
    __half2* l10 = l00 + (size_t)W * 4;                        // LO, (i1,j0)
    __half2* h00 = (__half2*)g_scratch + HI_OFF_H2 + p00 * 4;  // HI: +32MB
    __half2* h10 = h00 + (size_t)W * 4;

#define PACK4(dst, wgt, half)                                                   \
    {                                                                           \
        _Pragma("unroll")                                                       \
        for (int j = 0; j < 4; j++)                                             \
            dst[j] = __floats2half2_rn(v[8*(half) + 2*j]     * (wgt),           \
                                       v[8*(half) + 2*j + 1] * (wgt));          \
    }

    if (j0) {
        __half2 a[4], c[4];
        if (i0) { PACK4(a, w00, 0); red_v4h2(l00, a[0], a[1], a[2], a[3]); }
        if (i1) { PACK4(c, w10, 0); red_v4h2(l10, c[0], c[1], c[2], c[3]); }
        if (i0) { PACK4(a, w00, 1); red_v4h2(h00, a[0], a[1], a[2], a[3]); }
        if (i1) { PACK4(c, w10, 1); red_v4h2(h10, c[0], c[1], c[2], c[3]); }
    }
    if (j1) {
        __half2 a[4], c[4];
        if (i0) { PACK4(a, w01, 0); red_v4h2(l00 + 4, a[0], a[1], a[2], a[3]); }
        if (i1) { PACK4(c, w11, 0); red_v4h2(l10 + 4, c[0], c[1], c[2], c[3]); }
        if (i0) { PACK4(a, w01, 1); red_v4h2(h00 + 4, a[0], a[1], a[2], a[3]); }
        if (i1) { PACK4(c, w11, 1); red_v4h2(h10 + 4, c[0], c[1], c[2], c[3]); }
    }
#undef PACK4
}

// ---------------------------------------------------------------------------
// Role: zero 1024 pixels of scratch per block (both planes, 32 KiB/block).
// Plain stores (L2-allocating) on purpose: zeroed lines stay L2-resident and
// absorb the next kernel's REDs.
// ---------------------------------------------------------------------------
__device__ __forceinline__ void zero_role(int rb, int rt, int pix_base) {
    uint4* u = (uint4*)g_scratch;
    const uint4 z = make_uint4(0u, 0u, 0u, 0u);
#pragma unroll
    for (int k = 0; k < 4; k++) {
        int idx = pix_base + rb * 1024 + k * 256 + rt;   // coalesced
        u[idx]        = z;          // LO plane
        u[NPIX + idx] = z;          // HI plane
    }
}

// ---------------------------------------------------------------------------
// Role: transpose one 512-pixel tile (256 threads; R13 config).
// ---------------------------------------------------------------------------
__device__ __forceinline__ void transpose_role(int tb, int t, int b_base,
                                               float* __restrict__ out) {
    __shared__ __half2 sm[8][512];   // 16 KiB

    const __half2* s = (const __half2*)g_scratch;
    int b    = b_base + (tb >> 9);   // 512 tiles per batch
    int base = (tb & 511) * 512;     // pixel base within batch

#pragma unroll
    for (int q = 0; q < 2; q++) {
        int p = t + 256 * q;
        size_t gp = (size_t)b * HW + base + p;
        uint4 a  = __ldcs((const uint4*)(s + gp * 4));               // ch 0..7
        uint4 bq = __ldcs((const uint4*)(s + HI_OFF_H2 + gp * 4));   // ch 8..15
        sm[0][p] = *(__half2*)&a.x;  sm[1][p] = *(__half2*)&a.y;
        sm[2][p] = *(__half2*)&a.z;  sm[3][p] = *(__half2*)&a.w;
        sm[4][p] = *(__half2*)&bq.x; sm[5][p] = *(__half2*)&bq.y;
        sm[6][p] = *(__half2*)&bq.z; sm[7][p] = *(__half2*)&bq.w;
    }
    __syncthreads();

    float* ob = out + (size_t)b * CHW + base;
    int sub = t >> 7;                // 0: channel pairs 0..3, 1: pairs 4..7
    int tt  = t & 127;

#pragma unroll
    for (int r2 = 0; r2 < 4; r2++) {
        int r = sub * 4 + r2;
        uint4 raw = *(const uint4*)&sm[r][4 * tt];
        float2 f0 = __half22float2(*(__half2*)&raw.x);
        float2 f1 = __half22float2(*(__half2*)&raw.y);
        float2 f2 = __half22float2(*(__half2*)&raw.z);
        float2 f3 = __half22float2(*(__half2*)&raw.w);
        float4 ve = make_float4(f0.x, f1.x, f2.x, f3.x);  // channel 2r
        float4 vo = make_float4(f0.y, f1.y, f2.y, f3.y);  // channel 2r+1
        __stcs((float4*)(ob + (size_t)(2*r)     * HW) + tt, ve);
        __stcs((float4*)(ob + (size_t)(2*r + 1) * HW) + tt, vo);
    }
}

// ---------------------------------------------------------------------------
// K1: splat(batches 0-4)    || zero(scratch 5-7).           Disjoint data.
// K2: splat(batches 5-7)    || transpose(batches 0-4).      Disjoint data.
// K3: transpose(batches 5-7)|| zero(scratch 0-4, for next launch/replay).
// No cross-block waiting; kernel boundaries provide all ordering.
// ---------------------------------------------------------------------------
__global__ __launch_bounds__(256, 8)
void k1(const float* __restrict__ x, const float2* __restrict__ grid) {
    int bid = blockIdx.x;
    if (bid < A_SPLAT_BLKS) splat_pixel(x, grid, bid * 256 + threadIdx.x);
    else                    zero_role(bid - A_SPLAT_BLKS, threadIdx.x, A_PIX);
}

__global__ __launch_bounds__(256, 8)
void k2(const float* __restrict__ x, const float2* __restrict__ grid,
        float* __restrict__ out) {
    int bid = blockIdx.x;
    if (bid < B_SPLAT_BLKS) splat_pixel(x, grid, A_PIX + bid * 256 + threadIdx.x);
    else                    transpose_role(bid - B_SPLAT_BLKS, threadIdx.x, 0, out);
}

__global__ __launch_bounds__(256, 8)
void k3(float* __restrict__ out) {
    int bid = blockIdx.x;
    if (bid < B_TPOSE_BLKS) transpose_role(bid, threadIdx.x, BA, out);
    else                    zero_role(bid - B_TPOSE_BLKS, threadIdx.x, 0);
}

extern "C" void kernel_launch(void* const* d_in, const int* in_sizes, int n_in,
                              void* d_out, int out_size) {
    const float*  x    = (const float*)d_in[0];
    const float2* grid = (const float2*)d_in[1];
    float*        out  = (float*)d_out;

    k1<<<A_SPLAT_BLKS + B_ZERO_BLKS, 256>>>(x, grid);        // 5888 blocks
    k2<<<B_SPLAT_BLKS + A_TPOSE_BLKS, 256>>>(x, grid, out);  // 5632 blocks
    k3<<<B_TPOSE_BLKS + A_ZERO_BLKS, 256>>>(out);            // 2816 blocks
}